// round 11
// baseline (speedup 1.0000x reference)
#include <cuda_runtime.h>

#define B 512
#define N 512
#define NB 512
#define THREADS 512
#define FULL 0xffffffffu

// Cross-block accumulators (zero at load; last block resets for graph replay).
__device__ double             g_sum   = 0.0;
__device__ unsigned long long g_pairs = 0ULL;
__device__ unsigned int       g_done  = 0u;

// Monotone non-decreasing float -> bucket. Clamped ends are safe: the query
// exact-scans the threshold's own bucket.
__device__ __forceinline__ int bucket_of(float q) {
    float f = (q + 8.0f) * 32.0f;
    f = fminf(fmaxf(f, 0.0f), 511.0f);
    return (int)f;
}

__global__ void __launch_bounds__(THREADS)
fused_kernel(const float* __restrict__ scores,
             const unsigned int* __restrict__ labels,
             float* __restrict__ out) {
    __shared__ int   s_cnt[NB];        // histogram counts
    __shared__ float s_sum[NB];        // histogram sums
    __shared__ int   s_scnt[NB + 2];   // S[b] = count(bucket >= b); S[512] = 0
    __shared__ float s_ssum[NB + 2];   // Sm[b] = sum(bucket >= b)
    __shared__ int   s_cur[NB];        // scatter cursors (= S[b] - cnt[b])
    __shared__ float s_scat[N];        // negs in descending-bucket order
    __shared__ int   s_gtc[16];        // per-warp bucket-group count totals
    __shared__ float s_gts[16];        // per-warp bucket-group sum totals
    __shared__ float s_redf[16];
    __shared__ int   s_redi[16];

    const int row  = blockIdx.x;
    const int tid  = threadIdx.x;
    const int lane = tid & 31;
    const int wrp  = tid >> 5;
    const size_t gi = (size_t)row * N + tid;

    // ---- zero histogram; issue probe + score + speculative int32-view label
    // loads before the bar (all three are in-bounds under either dtype, so
    // their DRAM latencies overlap the detection barrier).
    s_cnt[tid] = 0;
    s_sum[tid] = 0.f;
    const unsigned int probe = labels[2 * tid + 1];   // first 4KB odd words
    const float        q     = scores[gi];
    const unsigned int uspec = labels[gi];            // valid if int32 labels

    const int any_odd = __syncthreads_or(probe != 0u);        // bar 1
    // odd words of the first 1KB+ are all-zero <=> labels are int64
    unsigned int u = uspec;
    if (!any_odd) u = labels[2 * gi];                 // int64: low word

    const bool neg = (u == 0u);
    const int  b   = bucket_of(q);

    // ---- histogram of negatives
    if (neg) { atomicAdd(&s_cnt[b], 1); atomicAdd(&s_sum[b], q); }
    __syncthreads();                                          // bar 2

    // ---- suffix scan; thread owns bucket tid, warp w owns [32w, 32w+32)
    const int   c = s_cnt[tid];
    const float m = s_sum[tid];
    int   sc = c;  float sm = m;          // inclusive suffix within warp group
    #pragma unroll
    for (int o = 1; o < 32; o <<= 1) {
        int   a  = __shfl_down_sync(FULL, sc, o);
        float bb = __shfl_down_sync(FULL, sm, o);
        if (lane + o < 32) { sc += a; sm += bb; }
    }
    if (lane == 0) { s_gtc[wrp] = sc; s_gts[wrp] = sm; }      // group totals
    __syncthreads();                                          // bar 3

    int   Wc = 0; float Wm = 0.f;         // totals of higher bucket groups
    #pragma unroll
    for (int g = 0; g < 16; g++) {
        if (g > wrp) { Wc += s_gtc[g]; Wm += s_gts[g]; }
    }
    const int   S  = sc + Wc;             // count(bucket >= tid)
    const float Sm = sm + Wm;
    s_scnt[tid] = S;
    s_ssum[tid] = Sm;
    s_cur[tid]  = S - c;                  // segment start for bucket tid
    if (tid == 0) { s_scnt[NB] = 0; s_ssum[NB] = 0.f; }
    __syncthreads();                                          // bar 4

    // ---- counting-sort scatter of negatives (descending bucket order)
    if (neg) s_scat[atomicAdd(&s_cur[b], 1)] = q;
    __syncthreads();                                          // bar 5

    // ---- query straight from registers (positives only)
    float acc = 0.0f;
    int nposl = 0;
    if (!neg) {
        const float t  = q - 1.0f;
        const int   bt = bucket_of(t);
        const int   st = s_scnt[bt + 1];  // count(bucket > bt): all exceed t
        const int   en = s_scnt[bt];      // end of bucket bt's segment
        float cg = (float)st;
        float sg = s_ssum[bt + 1];
        for (int j = st; j < en; j++) {   // exact scan of threshold bucket
            const float x = s_scat[j];
            if (x > t) { cg += 1.0f; sg += x; }
        }
        acc  = cg * (1.0f - q) + sg;
        nposl = 1;
    }

    // ---- reduce loss + npos
    #pragma unroll
    for (int o = 16; o > 0; o >>= 1) {
        acc   += __shfl_down_sync(FULL, acc, o);
        nposl += __shfl_down_sync(FULL, nposl, o);
    }
    if (lane == 0) { s_redf[wrp] = acc; s_redi[wrp] = nposl; }
    __syncthreads();                                          // bar 6

    // ---- single-level cross-block accumulate + last-block finalize
    if (tid == 0) {
        float vsum = 0.0f; int npos = 0;
        #pragma unroll
        for (int w = 0; w < 16; w++) { vsum += s_redf[w]; npos += s_redi[w]; }
        const int nneg = N - npos;

        atomicAdd(&g_sum, (double)vsum);
        atomicAdd(&g_pairs, (unsigned long long)npos * (unsigned long long)nneg);
        __threadfence();
        unsigned int ticket = atomicAdd(&g_done, 1u);
        if (ticket == B - 1) {
            __threadfence();
            double    s  = atomicAdd(&g_sum, 0.0);
            long long np = (long long)atomicAdd(&g_pairs, 0ULL);
            out[0] = (np > 0) ? (float)(s / (double)np) : 0.0f;
            g_sum   = 0.0;
            g_pairs = 0ULL;
            __threadfence();
            g_done  = 0u;
        }
    }
}

extern "C" void kernel_launch(void* const* d_in, const int* in_sizes, int n_in,
                              void* d_out, int out_size) {
    const float*        scores = (const float*)d_in[0];
    const unsigned int* labels = (const unsigned int*)d_in[1];
    float*              out    = (float*)d_out;

    fused_kernel<<<B, THREADS>>>(scores, labels, out);
}

// round 12
// speedup vs baseline: 1.1895x; 1.1895x over previous
#include <cuda_runtime.h>

#define B 512
#define N 512
#define NB 512
#define THREADS 256
#define FULL 0xffffffffu

// Cross-block accumulators (zero at load; last block resets for graph replay).
__device__ double             g_sum   = 0.0;
__device__ unsigned long long g_pairs = 0ULL;
__device__ unsigned int       g_done  = 0u;

// Monotone non-decreasing float -> bucket. Clamped ends are safe: the query
// exact-scans the threshold's own bucket.
__device__ __forceinline__ int bucket_of(float q) {
    float f = (q + 8.0f) * 32.0f;
    f = fminf(fmaxf(f, 0.0f), 511.0f);
    return (int)f;
}

__global__ void __launch_bounds__(THREADS)
fused_kernel(const float* __restrict__ scores,
             const unsigned int* __restrict__ labels,
             float* __restrict__ out) {
    __shared__ int   s_cnt[NB];        // histogram counts
    __shared__ float s_sum[NB];        // histogram sums
    __shared__ int   s_scnt[NB + 2];   // S[b] = count(bucket >= b); S[512] = 0
    __shared__ float s_ssum[NB + 2];   // Sm[b] = sum(bucket >= b)
    __shared__ int   s_cur[NB];        // scatter cursors (= S[b+1])
    __shared__ float s_scat[N];        // negs in descending-bucket order
    __shared__ int   s_gtc[8];         // per-warp bucket-group count totals
    __shared__ float s_gts[8];         // per-warp bucket-group sum totals
    __shared__ float s_redf[8];
    __shared__ int   s_redi[8];

    const int row  = blockIdx.x;
    const int tid  = threadIdx.x;
    const int lane = tid & 31;
    const int wrp  = tid >> 5;
    const size_t gi0 = (size_t)row * N + tid;
    const size_t gi1 = gi0 + 256;

    // ---- zero histogram; issue probe + scores + SPECULATIVE int32-view
    // label loads before the bar. The 32-bit reads at gi0/gi1 are in-bounds
    // under both dtypes (int64 buffer is 2x larger), so all 5 loads overlap
    // the detection barrier.
    s_cnt[tid] = 0;  s_cnt[tid + 256] = 0;
    s_sum[tid] = 0.f; s_sum[tid + 256] = 0.f;
    const unsigned int probe = labels[2 * tid + 1];
    const float q0 = scores[gi0];
    const float q1 = scores[gi1];
    const unsigned int spec0 = labels[gi0];   // valid iff labels are int32
    const unsigned int spec1 = labels[gi1];

    const int any_odd = __syncthreads_or(probe != 0u);        // bar 1
    unsigned int u0 = spec0, u1 = spec1;
    if (!any_odd) {                            // int64: low words
        u0 = labels[2 * gi0];
        u1 = labels[2 * gi1];
    }
    const bool neg0 = (u0 == 0u);
    const bool neg1 = (u1 == 0u);
    const int  b0 = bucket_of(q0);
    const int  b1 = bucket_of(q1);

    // ---- histogram of negatives
    if (neg0) { atomicAdd(&s_cnt[b0], 1); atomicAdd(&s_sum[b0], q0); }
    if (neg1) { atomicAdd(&s_cnt[b1], 1); atomicAdd(&s_sum[b1], q1); }
    __syncthreads();                                          // bar 2

    // ---- suffix scan; lane owns contiguous buckets {2*tid, 2*tid+1}
    const int2   ci = ((const int2*)s_cnt)[tid];
    const float2 mi = ((const float2*)s_sum)[tid];
    const int   c0 = ci.x,  c1 = ci.y;
    const float m0 = mi.x,  m1 = mi.y;
    const int   tot  = c0 + c1;
    const float totm = m0 + m1;

    int   sc = tot;   float sm = totm;    // inclusive suffix over lanes >= lane
    #pragma unroll
    for (int o = 1; o < 32; o <<= 1) {
        int   a = __shfl_down_sync(FULL, sc, o);
        float b = __shfl_down_sync(FULL, sm, o);
        if (lane + o < 32) { sc += a; sm += b; }
    }
    if (lane == 0) { s_gtc[wrp] = sc; s_gts[wrp] = sm; }      // warp totals
    __syncthreads();                                          // bar 3

    int   Wc = 0; float Wm = 0.f;         // totals of higher warps
    #pragma unroll
    for (int g = 0; g < 8; g++) {
        if (g > wrp) { Wc += s_gtc[g]; Wm += s_gts[g]; }
    }
    const int   T  = (sc - tot)  + Wc;    // suffix strictly above bucket 2t+1
    const float Tm = (sm - totm) + Wm;

    // S[2t] = c0+c1+T, S[2t+1] = c1+T; cursor[2t] = S[2t+1], cursor[2t+1] = T
    ((int2*)s_scnt)[tid]   = make_int2(tot + T, c1 + T);
    ((float2*)s_ssum)[tid] = make_float2(totm + Tm, m1 + Tm);
    ((int2*)s_cur)[tid]    = make_int2(c1 + T, T);
    if (tid == 255) { s_scnt[NB] = 0; s_ssum[NB] = 0.f; }
    __syncthreads();                                          // bar 4

    // ---- counting-sort scatter of negatives (descending bucket order)
    if (neg0) s_scat[atomicAdd(&s_cur[b0], 1)] = q0;
    if (neg1) s_scat[atomicAdd(&s_cur[b1], 1)] = q1;
    __syncthreads();                                          // bar 5

    // ---- queries straight from registers (positives only)
    float acc = 0.0f;
    #pragma unroll
    for (int e = 0; e < 2; e++) {
        const bool  isneg = e ? neg1 : neg0;
        const float p     = e ? q1   : q0;
        if (!isneg) {
            const float t = p - 1.0f;
            const int   b = bucket_of(t);
            const int  st = s_scnt[b + 1];     // count(bucket > b): all > t
            const int  en = s_scnt[b];
            float cg = (float)st;
            float sg = s_ssum[b + 1];
            for (int j = st; j < en; j++) {    // exact scan of bucket b
                const float q = s_scat[j];
                if (q > t) { cg += 1.0f; sg += q; }
            }
            acc += cg * (1.0f - p) + sg;
        }
    }

    // ---- reduce: loss via shfl, npos via ballot+popc (cheap)
    #pragma unroll
    for (int o = 16; o > 0; o >>= 1)
        acc += __shfl_down_sync(FULL, acc, o);
    const int wnpos = __popc(__ballot_sync(FULL, !neg0)) +
                      __popc(__ballot_sync(FULL, !neg1));
    if (lane == 0) { s_redf[wrp] = acc; s_redi[wrp] = wnpos; }
    __syncthreads();                                          // bar 6

    // ---- single-level cross-block accumulate + last-block finalize
    if (tid == 0) {
        float vsum = 0.0f; int npos = 0;
        #pragma unroll
        for (int w = 0; w < 8; w++) { vsum += s_redf[w]; npos += s_redi[w]; }
        const int nneg = N - npos;

        atomicAdd(&g_sum, (double)vsum);
        atomicAdd(&g_pairs, (unsigned long long)npos * (unsigned long long)nneg);
        __threadfence();
        unsigned int ticket = atomicAdd(&g_done, 1u);
        if (ticket == B - 1) {
            __threadfence();
            double    s  = atomicAdd(&g_sum, 0.0);
            long long np = (long long)atomicAdd(&g_pairs, 0ULL);
            out[0] = (np > 0) ? (float)(s / (double)np) : 0.0f;
            g_sum   = 0.0;
            g_pairs = 0ULL;
            __threadfence();
            g_done  = 0u;
        }
    }
}

extern "C" void kernel_launch(void* const* d_in, const int* in_sizes, int n_in,
                              void* d_out, int out_size) {
    const float*        scores = (const float*)d_in[0];
    const unsigned int* labels = (const unsigned int*)d_in[1];
    float*              out    = (float*)d_out;

    fused_kernel<<<B, THREADS>>>(scores, labels, out);
}